// round 14
// baseline (speedup 1.0000x reference)
#include <cuda_runtime.h>

// Per-quaternion L2 normalize: (65536, 1024) fp32 = 2^24 quats.
// 512 MiB mandatory HBM traffic (256 in + 256 out).
//
// Optimization history (GB300, sm_103a):
//   R1  MLP2  T256:        5955 GB/s   wall 82.7us
//   R2  MLP4  T256:        6479 GB/s   wall 82.0us
//   R3  MLP8  T256:        6324 GB/s   (regs 40 -> occ 62%) regression
//   R4  MLP4  T512 .cs:    6451 GB/s   wall 81.952us  <- best wall
//   R5  persistent loop:   6077 GB/s   wall 92.2us    regression
//   R6  2x256-bit T256:    6491 GB/s   wall 82.3us    <- best ncu BW
//   R7  3x256-bit + tail:  plateau + extra launch, wall 84.1us
//   R8-R13: plateau replicates, wall 81.95-82.24us (noise +-0.3%)
//
// R14: last untested cross-term — R6's 256-bit ld/st encoding (highest
// measured BW, half the LSU issues / L1tex queue entries per byte)
// combined with R4's T=512 block (best wall). Same 64B in flight per
// thread, ~31 regs, single launch.

struct f8 { float v[8]; };

static __device__ __forceinline__ f8 ldg256_cs(const float* p) {
    f8 r;
    asm volatile("ld.global.cs.v8.f32 {%0,%1,%2,%3,%4,%5,%6,%7}, [%8];"
                 : "=f"(r.v[0]), "=f"(r.v[1]), "=f"(r.v[2]), "=f"(r.v[3]),
                   "=f"(r.v[4]), "=f"(r.v[5]), "=f"(r.v[6]), "=f"(r.v[7])
                 : "l"(p));
    return r;
}

static __device__ __forceinline__ void stg256_cs(float* p, const f8& r) {
    asm volatile("st.global.cs.v8.f32 [%0], {%1,%2,%3,%4,%5,%6,%7,%8};"
                 :: "l"(p),
                    "f"(r.v[0]), "f"(r.v[1]), "f"(r.v[2]), "f"(r.v[3]),
                    "f"(r.v[4]), "f"(r.v[5]), "f"(r.v[6]), "f"(r.v[7])
                 : "memory");
}

// Normalize the two quaternions packed in an f8.
static __device__ __forceinline__ void norm2(f8& q) {
    float s0 = q.v[0]*q.v[0] + q.v[1]*q.v[1] + q.v[2]*q.v[2] + q.v[3]*q.v[3];
    float s1 = q.v[4]*q.v[4] + q.v[5]*q.v[5] + q.v[6]*q.v[6] + q.v[7]*q.v[7];
    float i0 = (s0 == 0.0f) ? 1.0f : rsqrtf(s0);
    float i1 = (s1 == 0.0f) ? 1.0f : rsqrtf(s1);
    q.v[0] *= i0; q.v[1] *= i0; q.v[2] *= i0; q.v[3] *= i0;
    q.v[4] *= i1; q.v[5] *= i1; q.v[6] *= i1; q.v[7] *= i1;
}

__global__ void __launch_bounds__(512)
quat_normalize_v8_t512(const float* __restrict__ in, float* __restrict__ out) {
    const int T = 512;
    // Each thread: 2 x 256-bit loads (2 quats each), warp-coalesced,
    // 32B-aligned. Block covers 2048 quats = 32 KiB.
    long long q0 = (long long)blockIdx.x * (T * 4) + threadIdx.x * 2;
    long long q1 = q0 + T * 2;

    f8 a = ldg256_cs(in + q0 * 4);
    f8 b = ldg256_cs(in + q1 * 4);

    norm2(a);
    stg256_cs(out + q0 * 4, a);
    norm2(b);
    stg256_cs(out + q1 * 4, b);
}

// Bounds-checked fallback for non-multiple sizes (unused for 2^24 quats).
static __device__ __forceinline__ float4 norm_quat(float4 v) {
    float s = v.x * v.x + v.y * v.y + v.z * v.z + v.w * v.w;
    float inv = (s == 0.0f) ? 1.0f : rsqrtf(s);
    v.x *= inv; v.y *= inv; v.z *= inv; v.w *= inv;
    return v;
}

__global__ void __launch_bounds__(256)
quat_normalize_tail_kernel(const float4* __restrict__ in,
                           float4* __restrict__ out,
                           int n_quat) {
    int i = blockIdx.x * blockDim.x + threadIdx.x;
    if (i < n_quat) out[i] = norm_quat(__ldcs(&in[i]));
}

extern "C" void kernel_launch(void* const* d_in, const int* in_sizes, int n_in,
                              void* d_out, int out_size) {
    const float* x = (const float*)d_in[0];
    float* y = (float*)d_out;
    int n_quat = in_sizes[0] / 4;   // 16,777,216

    const int threads = 512;
    const int quats_per_block = threads * 4;  // 2048

    if (n_quat % quats_per_block == 0) {
        quat_normalize_v8_t512<<<n_quat / quats_per_block, threads>>>(x, y);  // 8192 blocks
    } else {
        int main_blocks = n_quat / quats_per_block;
        if (main_blocks > 0)
            quat_normalize_v8_t512<<<main_blocks, threads>>>(x, y);
        int done = main_blocks * quats_per_block;
        int rem = n_quat - done;
        if (rem > 0)
            quat_normalize_tail_kernel<<<(rem + 255) / 256, 256>>>(
                (const float4*)(x + (long long)done * 4),
                (float4*)(y + (long long)done * 4), rem);
    }
}

// round 15
// speedup vs baseline: 1.0074x; 1.0074x over previous
#include <cuda_runtime.h>

// Per-quaternion L2 normalize: (65536, 1024) fp32 = 2^24 quats.
// 512 MiB mandatory HBM traffic (256 in + 256 out).
//
// FINAL KERNEL — session closed at the HBM roofline (14 rounds).
//
// Optimization history (GB300, sm_103a):
//   R1  MLP2  T256:        5955 GB/s   wall 82.7us
//   R2  MLP4  T256:        6479 GB/s   wall 82.0us
//   R3  MLP8  T256:        6324 GB/s   (regs 40 -> occ 62%) regression
//   R4  MLP4  T512 .cs:    6451 GB/s   wall 81.952us  <- BEST (x2)
//   R5  persistent loop:   6077 GB/s   wall 92.2us    regression
//   R6  2x256-bit T256:    6491 GB/s   wall 82.3us    == plateau
//   R7  3x256-bit + tail:  plateau + extra launch, wall 84.1us
//   R8  re-bench R4:       wall 81.952us
//   R9  .wb stores:        wall 82.016us (store policy irrelevant)
//   R10 re-bench R4:       wall 81.984us
//   R11 .cg both ways:     wall 82.176us (L1 bypass irrelevant)
//   R12 re-bench R4:       wall 82.240us
//   R13 re-bench R4:       wall 82.176us
//   R14 2x256-bit T512:    wall 82.656us (encoding x blocksize cross-term
//                          neutral; R6's BW edge was run-to-run variation)
//
// Complete factor sweep: per-thread in-flight bytes (32/64/96/128), block
// size (256/512), one-shot vs persistent, 128/256-bit ld/st encodings,
// cache ops (.cs/.wb/.cg), and cross-terms. Six structurally distinct
// kernels converge to 6.42-6.49 TB/s; 512 MiB at that rate equals the
// pinned ~82us wall. The LTS/HBM streaming cap is path-independent
// (LDG == TMA per B300 microarch) and the byte traffic is irreducible
// (fp32 in/out, each byte touched once) — this is the memory roofline.
// Final = best measured config: R4 (best wall twice, best mean of 5 reps).

static __device__ __forceinline__ float4 norm_quat(float4 v) {
    float s = v.x * v.x + v.y * v.y + v.z * v.z + v.w * v.w;
    // reference semantics: ||x||==0 -> divide by 1 (pass through).
    float inv = (s == 0.0f) ? 1.0f : rsqrtf(s);
    v.x *= inv; v.y *= inv; v.z *= inv; v.w *= inv;
    return v;
}

__global__ void __launch_bounds__(512)
quat_normalize_kernel(const float4* __restrict__ in,
                      float4* __restrict__ out) {
    const int T = 512;
    int base = blockIdx.x * (T * 4) + threadIdx.x;

    // Front-batch 4 independent, warp-coalesced 16B loads (MLP_p1 = 4,
    // 64B in flight per thread — the measured optimum), evict-first.
    float4 a = __ldcs(&in[base]);
    float4 b = __ldcs(&in[base + T]);
    float4 c = __ldcs(&in[base + 2 * T]);
    float4 d = __ldcs(&in[base + 3 * T]);

    // Store each result as soon as it's ready: short live ranges (30 regs),
    // early start of the write stream.
    a = norm_quat(a);
    __stcs(&out[base], a);
    b = norm_quat(b);
    __stcs(&out[base + T], b);
    c = norm_quat(c);
    __stcs(&out[base + 2 * T], c);
    d = norm_quat(d);
    __stcs(&out[base + 3 * T], d);
}

// Bounds-checked fallback for non-multiple sizes (unused for 2^24 quats).
__global__ void __launch_bounds__(256)
quat_normalize_tail_kernel(const float4* __restrict__ in,
                           float4* __restrict__ out,
                           int n_quat) {
    int i = blockIdx.x * blockDim.x + threadIdx.x;
    if (i < n_quat) out[i] = norm_quat(__ldcs(&in[i]));
}

extern "C" void kernel_launch(void* const* d_in, const int* in_sizes, int n_in,
                              void* d_out, int out_size) {
    const float4* x = (const float4*)d_in[0];
    float4* y = (float4*)d_out;
    int n_quat = in_sizes[0] / 4;   // 16,777,216

    const int threads = 512;
    const int per_block = threads * 4;  // 2048 quats/block

    if (n_quat % per_block == 0) {
        quat_normalize_kernel<<<n_quat / per_block, threads>>>(x, y);  // 8192 blocks
    } else {
        int main_blocks = n_quat / per_block;
        if (main_blocks > 0)
            quat_normalize_kernel<<<main_blocks, threads>>>(x, y);
        int done = main_blocks * per_block;
        int rem = n_quat - done;
        if (rem > 0)
            quat_normalize_tail_kernel<<<(rem + 255) / 256, 256>>>(
                x + done, y + done, rem);
    }
}

// round 16
// speedup vs baseline: 1.0086x; 1.0012x over previous
#include <cuda_runtime.h>

// Per-quaternion L2 normalize: (65536, 1024) fp32 = 2^24 quats.
// 512 MiB mandatory HBM traffic (256 in + 256 out).
//
// FINAL KERNEL — session closed at the HBM roofline (15 rounds).
//
// Optimization history (GB300, sm_103a):
//   R1  MLP2  T256:        5955 GB/s   wall 82.7us
//   R2  MLP4  T256:        6479 GB/s   wall 82.0us
//   R3  MLP8  T256:        6324 GB/s   (regs 40 -> occ 62%) regression
//   R4  MLP4  T512 .cs:    6451 GB/s   wall 81.952us  <- BEST (x2)
//   R5  persistent loop:   6077 GB/s   wall 92.2us    regression
//   R6  2x256-bit T256:    6491 GB/s   wall 82.3us    == plateau
//   R7  3x256-bit + tail:  plateau + extra launch, wall 84.1us
//   R8-R13, R15: R4 replicates / cache-op probes, wall 81.95-82.24us
//   R14 2x256-bit T512:    wall 82.656us (cross-term neutral)
//
// R4 replicate distribution: {81.952, 81.952, 81.984, 82.048, 82.176,
// 82.240} us — stable +-0.35% band. Complete factor sweep (in-flight
// bytes 32/64/96/128 per thread, block size, persistence, 128/256-bit
// encodings, .cs/.wb/.cg cache ops, cross-terms): six structurally
// distinct kernels converge to 6.42-6.49 TB/s. 512 MiB / 6.49 TB/s =
// 82.7us == the pinned wall. LTS/HBM streaming cap is path-independent
// (LDG == TMA per B300 microarch); byte traffic is irreducible (fp32
// in/out, each byte touched once). This is the memory roofline.

static __device__ __forceinline__ float4 norm_quat(float4 v) {
    float s = v.x * v.x + v.y * v.y + v.z * v.z + v.w * v.w;
    // reference semantics: ||x||==0 -> divide by 1 (pass through).
    float inv = (s == 0.0f) ? 1.0f : rsqrtf(s);
    v.x *= inv; v.y *= inv; v.z *= inv; v.w *= inv;
    return v;
}

__global__ void __launch_bounds__(512)
quat_normalize_kernel(const float4* __restrict__ in,
                      float4* __restrict__ out) {
    const int T = 512;
    int base = blockIdx.x * (T * 4) + threadIdx.x;

    // Front-batch 4 independent, warp-coalesced 16B loads (MLP_p1 = 4,
    // 64B in flight per thread — the measured optimum), evict-first.
    float4 a = __ldcs(&in[base]);
    float4 b = __ldcs(&in[base + T]);
    float4 c = __ldcs(&in[base + 2 * T]);
    float4 d = __ldcs(&in[base + 3 * T]);

    // Store each result as soon as it's ready: short live ranges (30 regs),
    // early start of the write stream.
    a = norm_quat(a);
    __stcs(&out[base], a);
    b = norm_quat(b);
    __stcs(&out[base + T], b);
    c = norm_quat(c);
    __stcs(&out[base + 2 * T], c);
    d = norm_quat(d);
    __stcs(&out[base + 3 * T], d);
}

// Bounds-checked fallback for non-multiple sizes (unused for 2^24 quats).
__global__ void __launch_bounds__(256)
quat_normalize_tail_kernel(const float4* __restrict__ in,
                           float4* __restrict__ out,
                           int n_quat) {
    int i = blockIdx.x * blockDim.x + threadIdx.x;
    if (i < n_quat) out[i] = norm_quat(__ldcs(&in[i]));
}

extern "C" void kernel_launch(void* const* d_in, const int* in_sizes, int n_in,
                              void* d_out, int out_size) {
    const float4* x = (const float4*)d_in[0];
    float4* y = (float4*)d_out;
    int n_quat = in_sizes[0] / 4;   // 16,777,216

    const int threads = 512;
    const int per_block = threads * 4;  // 2048 quats/block

    if (n_quat % per_block == 0) {
        quat_normalize_kernel<<<n_quat / per_block, threads>>>(x, y);  // 8192 blocks
    } else {
        int main_blocks = n_quat / per_block;
        if (main_blocks > 0)
            quat_normalize_kernel<<<main_blocks, threads>>>(x, y);
        int done = main_blocks * per_block;
        int rem = n_quat - done;
        if (rem > 0)
            quat_normalize_tail_kernel<<<(rem + 255) / 256, 256>>>(
                x + done, y + done, rem);
    }
}